// round 2
// baseline (speedup 1.0000x reference)
#include <cuda_runtime.h>
#include <math.h>

#define BS 1024
#define SL 512
#define TT 64

// Per-batch partials (static device globals: no allocation). Every element is
// written on every launch -> deterministic, no zero-init needed.
__device__ float g_score[BS];
__device__ float g_logZ[BS];
__device__ int   g_count[BS];

// ---------------------------------------------------------------------------
// Score kernel: per-batch tag-path score + mask count.
//   score_b = st[tag0] + e[b,0,tag0]
//           + sum_{s>=1} mask[b,s]*(t[tag_{s-1},tag_s] + e[b,s,tag_s])
//           + et[tag_{last}],  last = count-1
// ---------------------------------------------------------------------------
__global__ void crf_score_kernel(const float* __restrict__ e,
                                 const int* __restrict__ tags,
                                 const unsigned char* __restrict__ mask,
                                 const float* __restrict__ st,
                                 const float* __restrict__ et,
                                 const float* __restrict__ t)
{
    const int b = blockIdx.x;
    const int tid = threadIdx.x;               // 128 threads
    const int* tg = tags + b * SL;
    const unsigned char* mk = mask + b * SL;
    const float* eb = e + (size_t)b * SL * TT;

    float s_local = 0.f;
    int c_local = 0;
    for (int s = tid; s < SL; s += 128) {
        int tag = tg[s];
        int m = mk[s] ? 1 : 0;
        if (s == 0) {
            s_local += st[tag] + eb[tag];
        } else if (m) {
            int tp = tg[s - 1];
            s_local += t[tp * TT + tag] + eb[(size_t)s * TT + tag];
        }
        c_local += m;
    }

    __shared__ float ssum[128];
    __shared__ int   scnt[128];
    ssum[tid] = s_local;
    scnt[tid] = c_local;
    __syncthreads();
    for (int off = 64; off > 0; off >>= 1) {
        if (tid < off) {
            ssum[tid] += ssum[tid + off];
            scnt[tid] += scnt[tid + off];
        }
        __syncthreads();
    }
    if (tid == 0) {
        float sc = ssum[0];
        int cnt = scnt[0];
        if (cnt > 0) sc += et[tg[cnt - 1]];
        g_score[b] = sc;
        g_count[b] = cnt;
    }
}

// ---------------------------------------------------------------------------
// Forward (partition function) kernel: one block of 64 threads per batch.
// Thread j owns state c[j] (centered log-alpha) and a register-resident
// column P[i] = exp(t[i][j]).
// Recurrence: norm[j] = log(sum_i exp(norm_old[i]) * P[i][j]) + e[s][j]
// kept as c[j] + base, rebasing by lga0 = log(a_sm[0]) each step (exact).
// ---------------------------------------------------------------------------
__global__ void __launch_bounds__(TT)
crf_forward_kernel(const float* __restrict__ e,
                   const unsigned char* __restrict__ mask,
                   const float* __restrict__ st,
                   const float* __restrict__ et,
                   const float* __restrict__ t)
{
    const int b = blockIdx.x;
    const int j = threadIdx.x;                 // 64 threads, j = state index

    __shared__ float a_sm[2][TT];
    __shared__ float wred[4];

    // P column j in registers (loop-invariant for all 511 steps).
    float P[TT];
#pragma unroll
    for (int i = 0; i < TT; i++) P[i] = expf(t[i * TT + j]);

    const float* eb = e + (size_t)b * SL * TT;
    const unsigned char* mk = mask + b * SL;

    float c = st[j] + eb[j];                   // step 0 init
    float base = 0.f;
    float ecur = eb[TT + j];                   // prefetch e for s=1
    int par = 0;

    for (int s = 1; s < SL; ++s) {
        float a = __expf(c);
        a_sm[par][j] = a;
        __syncthreads();

        // Prefetch e for the next step (hides LDG latency behind the dot).
        float enext = 0.f;
        if (s + 1 < SL) enext = eb[(size_t)(s + 1) * TT + j];
        int m = mk[s] ? 1 : 0;                 // uniform across the block

        const float4* av = (const float4*)a_sm[par];
        float acc0 = 0.f, acc1 = 0.f, acc2 = 0.f, acc3 = 0.f;
#pragma unroll
        for (int q = 0; q < TT / 4; q++) {
            float4 v = av[q];                  // broadcast LDS.128
            acc0 = fmaf(v.x, P[4 * q + 0], acc0);
            acc1 = fmaf(v.y, P[4 * q + 1], acc1);
            acc2 = fmaf(v.z, P[4 * q + 2], acc2);
            acc3 = fmaf(v.w, P[4 * q + 3], acc3);
        }
        float sum = (acc0 + acc1) + (acc2 + acc3);
        float lga0 = __logf(a_sm[par][0]);     // rebase anchor (uniform)

        if (m) {
            c = __logf(sum) - lga0 + ecur;
            base += lga0;
        }
        ecur = enext;
        par ^= 1;                              // double buffer -> 1 BAR/step
    }

    // logZ_b = base + LSE_j(c[j] + et[j])
    float v = c + et[j];
    const int lane = j & 31;
    const int wid = j >> 5;

    float m1 = v;
#pragma unroll
    for (int off = 16; off > 0; off >>= 1)
        m1 = fmaxf(m1, __shfl_xor_sync(0xffffffffu, m1, off));
    if (lane == 0) wred[wid] = m1;
    __syncthreads();
    float gmax = fmaxf(wred[0], wred[1]);

    float se = __expf(v - gmax);
#pragma unroll
    for (int off = 16; off > 0; off >>= 1)
        se += __shfl_xor_sync(0xffffffffu, se, off);
    if (lane == 0) wred[2 + wid] = se;
    __syncthreads();

    if (j == 0) {
        float stot = wred[2] + wred[3];
        g_logZ[b] = base + gmax + __logf(stot);
    }
}

// ---------------------------------------------------------------------------
// Deterministic final reduction: out = sum_b(score_b - logZ_b) / sum(mask)
// ---------------------------------------------------------------------------
__global__ void crf_finalize_kernel(float* __restrict__ out)
{
    const int tid = threadIdx.x;               // 256 threads
    float num = 0.f, tot = 0.f;
    for (int b = tid; b < BS; b += 256) {
        num += g_score[b] - g_logZ[b];
        tot += (float)g_count[b];
    }
    __shared__ float sn[256], stt[256];
    sn[tid] = num;
    stt[tid] = tot;
    __syncthreads();
    for (int off = 128; off > 0; off >>= 1) {
        if (tid < off) {
            sn[tid]  += sn[tid + off];
            stt[tid] += stt[tid + off];
        }
        __syncthreads();
    }
    if (tid == 0) out[0] = sn[0] / stt[0];
}

// ---------------------------------------------------------------------------
// Inputs (metadata order): e(f32), tags(i32), mask(bool->u8), st(f32),
// et(f32), t(f32). Output: single f32 scalar.
// ---------------------------------------------------------------------------
extern "C" void kernel_launch(void* const* d_in, const int* in_sizes, int n_in,
                              void* d_out, int out_size)
{
    const float*         e    = (const float*)d_in[0];
    const int*           tags = (const int*)d_in[1];
    const unsigned char* mask = (const unsigned char*)d_in[2];
    const float*         st   = (const float*)d_in[3];
    const float*         et   = (const float*)d_in[4];
    const float*         t    = (const float*)d_in[5];
    float* out = (float*)d_out;

    crf_score_kernel<<<BS, 128>>>(e, tags, mask, st, et, t);
    crf_forward_kernel<<<BS, TT>>>(e, mask, st, et, t);
    crf_finalize_kernel<<<1, 256>>>(out);
}